// round 13
// baseline (speedup 1.0000x reference)
#include <cuda_runtime.h>
#include <cuda_fp16.h>
#include <cuda_bf16.h>
#include <cstdint>

#define NN 100000
#define EE 1600000
#define HH 128
#define OUTC 40

typedef unsigned long long u64;
typedef unsigned int u32;

// ---------------- static device scratch (allocation-free rule) ----------------
__device__ __half g_h [(size_t)NN * HH];  // xW (layer1 then layer2), fp16 storage
__device__ __half g_x1[(size_t)NN * HH];  // relu(bn1(gcn1)), fp16 storage
__device__ __half g_x2[(size_t)NN * HH];  // relu(bn2(gcn2)), fp16 storage
__device__ float  g_dinv[NN];
__device__ int    g_deg[NN];              // zeroed after consumption each call
__device__ int    g_rowptr[NN + 1];
__device__ int    g_cursor[NN];
__device__ uint2  g_cw[EE];               // packed (col, weight-bits) per edge
__device__ int    g_bsum[128];
// global spin-barrier state (generation-based; monotonic across replays)
__device__ volatile int g_bar_count;
__device__ volatile int g_bar_gen;
// FRAGMENT-MAJOR bf16 hi/lo images of W1/W2 B-operand
__device__ __align__(16) u32 g_Bh1[8192];
__device__ __align__(16) u32 g_Bl1[8192];
__device__ __align__(16) u32 g_Bh2[8192];
__device__ __align__(16) u32 g_Bl2[8192];

// ---------------- f32x2 helpers ----------------
__device__ __forceinline__ u64 pack2_dup(float v) {
    u64 r; asm("mov.b64 %0, {%1, %1};" : "=l"(r) : "f"(v)); return r;
}
__device__ __forceinline__ void ffma2(u64 &d, u64 a, u64 b) {
    asm("fma.rn.f32x2 %0, %1, %2, %0;" : "+l"(d) : "l"(a), "l"(b));
}

// ---------------- mma.sync bf16 (m16n8k16, fp32 accum) ----------------
__device__ __forceinline__ void mma_bf16(float* c, const u32* a, const u32* b) {
    asm volatile(
        "mma.sync.aligned.m16n8k16.row.col.f32.bf16.bf16.f32 "
        "{%0,%1,%2,%3}, {%4,%5,%6,%7}, {%8,%9}, {%0,%1,%2,%3};"
        : "+f"(c[0]), "+f"(c[1]), "+f"(c[2]), "+f"(c[3])
        : "r"(a[0]), "r"(a[1]), "r"(a[2]), "r"(a[3]), "r"(b[0]), "r"(b[1]));
}

// ---------------- bprep body: W[k][n] fp32 -> fragment-major bf16 hi/lo ------------
__device__ __forceinline__ void bprep_body(const float* __restrict__ W, int sel, int i) {
    __nv_bfloat16* bh = (__nv_bfloat16*)(sel ? g_Bh2 : g_Bh1);
    __nv_bfloat16* bl = (__nv_bfloat16*)(sel ? g_Bl2 : g_Bl1);
    int k = i >> 7, n = i & 127;
    float v = W[i];
    __nv_bfloat16 h = __float2bfloat16(v);
    __nv_bfloat16 l = __float2bfloat16(v - __bfloat162float(h));
    int w   = n >> 4;
    int nt  = (n >> 3) & 1;
    int g   = n & 7;
    int kp  = k >> 1;
    int kt  = kp >> 3;
    int kpj = kp & 7;
    int b4  = kpj & 3;
    int reg = kpj >> 2;
    int lane = g * 4 + b4;
    int idx = (((w * 8 + kt) * 32 + lane) * 4 + nt * 2 + reg) * 2 + (k & 1);
    bh[idx] = h;
    bl[idx] = l;
}

// ---------------- prep: bprep(W1) + bprep(W2) + histo, merged by block range --------
__global__ void prep(const float* __restrict__ W1, const float* __restrict__ W2,
                     const int* __restrict__ rows, int e) {
    int b = blockIdx.x;
    if (b < 64) {
        bprep_body(W1, 0, b * 256 + threadIdx.x);
    } else if (b < 128) {
        bprep_body(W2, 1, (b - 64) * 256 + threadIdx.x);
    } else {
        int i = (b - 128) * 256 + threadIdx.x;
        if (i < e) atomicAdd(&g_deg[rows[i]], 1);
    }
}

// ---------------- fused CSR build: scan + offsets + scatter (one launch) -----------
// 98 blocks x 1024, all co-resident (2 blocks/SM x 148 SMs = 296 slots).
// Generation-based global barrier: standard arrive/release with fences.
__device__ __forceinline__ void grid_bar(int nblocks) {
    __syncthreads();
    if (threadIdx.x == 0) {
        int gen = g_bar_gen;
        __threadfence();
        if (atomicAdd((int*)&g_bar_count, 1) == nblocks - 1) {
            g_bar_count = 0;
            __threadfence();
            g_bar_gen = gen + 1;
        } else {
            while (g_bar_gen == gen) { }
            __threadfence();
        }
    }
    __syncthreads();
}

__global__ __launch_bounds__(1024) void csr_fused(const int* __restrict__ rows,
                                                  const int* __restrict__ cols,
                                                  int n, int e, int nblocks) {
    __shared__ int s[1024];
    __shared__ int s2[128];
    int b = blockIdx.x;
    int t = threadIdx.x;
    int i = b * 1024 + t;

    // phase 1: per-block inclusive scan of degrees
    int v = (i < n) ? g_deg[i] : 0;
    s[t] = v;
    __syncthreads();
    for (int off = 1; off < 1024; off <<= 1) {
        int u = (t >= off) ? s[t - off] : 0;
        __syncthreads();
        s[t] += u;
        __syncthreads();
    }
    if (i < n) g_rowptr[i] = s[t] - v;        // block-local exclusive
    if (t == 1023) g_bsum[b] = s[1023];       // block total

    grid_bar(nblocks);

    // phase 2: every block scans the <=128 block totals redundantly
    if (t < 128) s2[t] = (t < nblocks) ? g_bsum[t] : 0;
    __syncthreads();
    for (int off = 1; off < 128; off <<= 1) {
        int u = (t < 128 && t >= off) ? s2[t - off] : 0;
        __syncthreads();
        if (t < 128) s2[t] += u;              // inclusive
        __syncthreads();
    }
    if (i < n) {
        int pre = (b == 0) ? 0 : s2[b - 1];   // exclusive block offset
        int val = g_rowptr[i] + pre;
        g_rowptr[i] = val;
        g_cursor[i] = val;
        g_dinv[i]   = rsqrtf((float)v + 1.0f);
        g_deg[i]    = 0;                       // ready for next call's histo
    }
    if (i == 0) g_rowptr[n] = e;

    grid_bar(nblocks);

    // phase 3: scatter edges (grid-stride)
    int stride = nblocks * 1024;
    for (int jj = b * 1024 + t; jj < e; jj += stride) {
        int r = rows[jj];
        int c = cols[jj];
        int p = atomicAdd(&g_cursor[r], 1);
        g_cw[p] = make_uint2((u32)c, __float_as_uint(g_dinv[r] * g_dinv[c]));
    }
}

// ---------------- tensor GEMM: g_h[M,128](fp16) = A[M,128] @ W ----------------
#define SM_GT 65536

__global__ __launch_bounds__(256) void gemm_mma(int a_sel, const float* __restrict__ Aext,
                                                int b_sel, int M) {
    extern __shared__ u32 sm[];
    u32* sAh = sm;            // 8192 u32
    u32* sAl = sm + 8192;     // 8192 u32

    const uint4* __restrict__ B4h = (const uint4*)(b_sel ? g_Bh2 : g_Bh1);
    const uint4* __restrict__ B4l = (const uint4*)(b_sel ? g_Bl2 : g_Bl1);

    int tid = threadIdx.x;
    int bm  = blockIdx.x * 128;

    for (int i = tid; i < 8192; i += 256) {
        int row = i >> 6, kpair = i & 63;
        int gm = bm + row; if (gm >= M) gm = M - 1;
        float2 v;
        if (a_sel) {
            __half2 hv = *(const __half2*)&g_x1[(size_t)gm * 128 + 2 * kpair];
            v = __half22float2(hv);
        } else {
            v = *(const float2*)&Aext[(size_t)gm * 128 + 2 * kpair];
        }
        __nv_bfloat16 hx = __float2bfloat16(v.x);
        __nv_bfloat16 hy = __float2bfloat16(v.y);
        __nv_bfloat16 lx = __float2bfloat16(v.x - __bfloat162float(hx));
        __nv_bfloat16 ly = __float2bfloat16(v.y - __bfloat162float(hy));
        int mt = row >> 4;
        int r  = row & 15;
        int g  = r & 7;
        int kt  = kpair >> 3;
        int kpj = kpair & 7;
        int b4  = kpj & 3;
        int reg = (r >> 3) | ((kpj >> 2) << 1);
        int lane = g * 4 + b4;
        int idx = ((mt * 8 + kt) * 32 + lane) * 4 + reg;
        __nv_bfloat162 ph = __halves2bfloat162(hx, hy);
        __nv_bfloat162 pl = __halves2bfloat162(lx, ly);
        sAh[idx] = *(u32*)&ph;
        sAl[idx] = *(u32*)&pl;
    }
    __syncthreads();

    int w = tid >> 5;
    int l = tid & 31;
    int g  = l >> 2;
    int b4 = l & 3;
    int nbase = w * 16;

    float c[8][2][4];
#pragma unroll
    for (int mt = 0; mt < 8; mt++)
#pragma unroll
        for (int nt = 0; nt < 2; nt++)
#pragma unroll
            for (int q = 0; q < 4; q++) c[mt][nt][q] = 0.f;

#pragma unroll
    for (int kt = 0; kt < 8; kt++) {
        int bidx = (w * 8 + kt) * 32 + l;
        uint4 bhv = B4h[bidx];
        uint4 blv = B4l[bidx];
        u32 bh0[2] = {bhv.x, bhv.y};
        u32 bh1[2] = {bhv.z, bhv.w};
        u32 bl0[2] = {blv.x, blv.y};
        u32 bl1[2] = {blv.z, blv.w};
#pragma unroll
        for (int mt = 0; mt < 8; mt++) {
            int aidx = ((mt * 8 + kt) * 32 + l) * 4;
            uint4 ahv = *(const uint4*)&sAh[aidx];
            uint4 alv = *(const uint4*)&sAl[aidx];
            u32 ah[4] = {ahv.x, ahv.y, ahv.z, ahv.w};
            u32 al[4] = {alv.x, alv.y, alv.z, alv.w};
            mma_bf16(c[mt][0], ah, bh0);
            mma_bf16(c[mt][0], al, bh0);
            mma_bf16(c[mt][0], ah, bl0);
            mma_bf16(c[mt][1], ah, bh1);
            mma_bf16(c[mt][1], al, bh1);
            mma_bf16(c[mt][1], ah, bl1);
        }
    }

#pragma unroll
    for (int mt = 0; mt < 8; mt++) {
        int gm0 = bm + mt * 16 + g;
        int gm1 = gm0 + 8;
#pragma unroll
        for (int nt = 0; nt < 2; nt++) {
            int col = nbase + nt * 8 + b4 * 2;
            if (gm0 < M)
                *(__half2*)&g_h[(size_t)gm0 * 128 + col] = __floats2half2_rn(c[mt][nt][0], c[mt][nt][1]);
            if (gm1 < M)
                *(__half2*)&g_h[(size_t)gm1 * 128 + col] = __floats2half2_rn(c[mt][nt][2], c[mt][nt][3]);
        }
    }
}

// ---------------- gather aggregation + bias + BN + ReLU ----------------
__device__ __forceinline__ void acc_edge(float* acc, uint4 r, float w) {
#pragma unroll
    for (int q = 0; q < 4; q++) {
        float2 f = __half22float2(((const __half2*)&r)[q]);
        acc[2 * q]     += f.x * w;
        acc[2 * q + 1] += f.y * w;
    }
}

__global__ __launch_bounds__(256) void aggregate(const float* __restrict__ bias,
                          const float* __restrict__ gamma,
                          const float* __restrict__ beta,
                          const float* __restrict__ mean,
                          const float* __restrict__ var,
                          int dst_sel, int n) {
    int node = (blockIdx.x * blockDim.x + threadIdx.x) >> 4;
    if (node >= n) return;
    int lane = threadIdx.x & 15;
    int c0   = lane << 3;

    float di    = g_dinv[node];
    int   start = g_rowptr[node];
    int   end   = g_rowptr[node + 1];

    float acc[8];
#pragma unroll
    for (int q = 0; q < 8; q++) acc[q] = 0.f;

    int j = start;
    for (; j + 7 < end; j += 8) {
        uint2 e0 = g_cw[j + 0], e1 = g_cw[j + 1], e2 = g_cw[j + 2], e3 = g_cw[j + 3];
        uint2 e4 = g_cw[j + 4], e5 = g_cw[j + 5], e6 = g_cw[j + 6], e7 = g_cw[j + 7];
        uint4 r0 = *(const uint4*)&g_h[(size_t)e0.x * 128 + c0];
        uint4 r1 = *(const uint4*)&g_h[(size_t)e1.x * 128 + c0];
        uint4 r2 = *(const uint4*)&g_h[(size_t)e2.x * 128 + c0];
        uint4 r3 = *(const uint4*)&g_h[(size_t)e3.x * 128 + c0];
        uint4 r4 = *(const uint4*)&g_h[(size_t)e4.x * 128 + c0];
        uint4 r5 = *(const uint4*)&g_h[(size_t)e5.x * 128 + c0];
        uint4 r6 = *(const uint4*)&g_h[(size_t)e6.x * 128 + c0];
        uint4 r7 = *(const uint4*)&g_h[(size_t)e7.x * 128 + c0];
        acc_edge(acc, r0, __uint_as_float(e0.y));
        acc_edge(acc, r1, __uint_as_float(e1.y));
        acc_edge(acc, r2, __uint_as_float(e2.y));
        acc_edge(acc, r3, __uint_as_float(e3.y));
        acc_edge(acc, r4, __uint_as_float(e4.y));
        acc_edge(acc, r5, __uint_as_float(e5.y));
        acc_edge(acc, r6, __uint_as_float(e6.y));
        acc_edge(acc, r7, __uint_as_float(e7.y));
    }
    for (; j + 3 < end; j += 4) {
        uint2 e0 = g_cw[j + 0], e1 = g_cw[j + 1], e2 = g_cw[j + 2], e3 = g_cw[j + 3];
        uint4 r0 = *(const uint4*)&g_h[(size_t)e0.x * 128 + c0];
        uint4 r1 = *(const uint4*)&g_h[(size_t)e1.x * 128 + c0];
        uint4 r2 = *(const uint4*)&g_h[(size_t)e2.x * 128 + c0];
        uint4 r3 = *(const uint4*)&g_h[(size_t)e3.x * 128 + c0];
        acc_edge(acc, r0, __uint_as_float(e0.y));
        acc_edge(acc, r1, __uint_as_float(e1.y));
        acc_edge(acc, r2, __uint_as_float(e2.y));
        acc_edge(acc, r3, __uint_as_float(e3.y));
    }
    for (; j < end; j++) {
        uint2 e0 = g_cw[j];
        uint4 r0 = *(const uint4*)&g_h[(size_t)e0.x * 128 + c0];
        acc_edge(acc, r0, __uint_as_float(e0.y));
    }
    {
        uint4 rs = *(const uint4*)&g_h[(size_t)node * 128 + c0];
        acc_edge(acc, rs, di * di);
    }

    __half* __restrict__ out = (dst_sel == 1) ? g_x1 : g_x2;
    union { __half2 h2[4]; uint4 v; } pk;
#pragma unroll
    for (int h = 0; h < 2; h++) {
        int c = c0 + h * 4;
        float4 bb = *(const float4*)&bias[c];
        float4 gg = *(const float4*)&gamma[c];
        float4 be = *(const float4*)&beta[c];
        float4 mm = *(const float4*)&mean[c];
        float4 vv = *(const float4*)&var[c];
        float s0 = gg.x * rsqrtf(vv.x + 1e-5f);
        float s1 = gg.y * rsqrtf(vv.y + 1e-5f);
        float s2 = gg.z * rsqrtf(vv.z + 1e-5f);
        float s3 = gg.w * rsqrtf(vv.w + 1e-5f);
        float y0 = fmaxf((acc[4 * h + 0] + bb.x - mm.x) * s0 + be.x, 0.0f);
        float y1 = fmaxf((acc[4 * h + 1] + bb.y - mm.y) * s1 + be.y, 0.0f);
        float y2 = fmaxf((acc[4 * h + 2] + bb.z - mm.z) * s2 + be.z, 0.0f);
        float y3 = fmaxf((acc[4 * h + 3] + bb.w - mm.w) * s3 + be.w, 0.0f);
        pk.h2[2 * h]     = __floats2half2_rn(y0, y1);
        pk.h2[2 * h + 1] = __floats2half2_rn(y2, y3);
    }
    *(uint4*)&out[(size_t)node * 128 + c0] = pk.v;
}

// ---------------- final FC: out = [x0 | x1 | x2] @ fc_W + fc_b, f32x2 inner ----------------
__global__ void fc_kernel(const float* __restrict__ x0,
                          const float* __restrict__ W,
                          const float* __restrict__ bias,
                          float* __restrict__ out, int n) {
    __shared__ float Ws[128 * 40];
    __shared__ float St[32 * 130];

    int tid = threadIdx.x;
    int r   = tid / 5;
    int cg  = (tid % 5) * 8;
    int row = blockIdx.x * 32 + r;

    u64 acc[4];
    {
        ulonglong2 b0 = *(const ulonglong2*)&bias[cg];
        ulonglong2 b1 = *(const ulonglong2*)&bias[cg + 4];
        acc[0] = b0.x; acc[1] = b0.y; acc[2] = b1.x; acc[3] = b1.y;
    }

    for (int s = 0; s < 3; s++) {
        __syncthreads();
        for (int i = tid; i < 1280; i += 160)
            ((float4*)Ws)[i] = ((const float4*)W)[s * 1280 + i];
        for (int i = tid; i < 1024; i += 160) {
            int rr = i >> 5;
            int kk = (i & 31) << 2;
            int gr = blockIdx.x * 32 + rr;
            float4 v;
            if (gr < n) {
                if (s == 0) {
                    v = *(const float4*)&x0[(size_t)gr * 128 + kk];
                } else {
                    const __half* S = (s == 1) ? g_x1 : g_x2;
                    uint2 hv = *(const uint2*)&S[(size_t)gr * 128 + kk];
                    float2 f0 = __half22float2(*(__half2*)&hv.x);
                    float2 f1 = __half22float2(*(__half2*)&hv.y);
                    v = make_float4(f0.x, f0.y, f1.x, f1.y);
                }
            } else {
                v = make_float4(0.f, 0.f, 0.f, 0.f);
            }
            St[rr * 130 + kk + 0] = v.x;
            St[rr * 130 + kk + 1] = v.y;
            St[rr * 130 + kk + 2] = v.z;
            St[rr * 130 + kk + 3] = v.w;
        }
        __syncthreads();
#pragma unroll 4
        for (int k = 0; k < 128; k++) {
            u64 a2 = pack2_dup(St[r * 130 + k]);
            const float* wr = &Ws[k * 40 + cg];
            ulonglong2 w0 = *(const ulonglong2*)(wr);
            ulonglong2 w1 = *(const ulonglong2*)(wr + 4);
            ffma2(acc[0], a2, w0.x);
            ffma2(acc[1], a2, w0.y);
            ffma2(acc[2], a2, w1.x);
            ffma2(acc[3], a2, w1.y);
        }
    }
    if (row < n) {
        *(ulonglong2*)&out[(size_t)row * 40 + cg]     = make_ulonglong2(acc[0], acc[1]);
        *(ulonglong2*)&out[(size_t)row * 40 + cg + 4] = make_ulonglong2(acc[2], acc[3]);
    }
}

// ---------------- launch ----------------
extern "C" void kernel_launch(void* const* d_in, const int* in_sizes, int n_in,
                              void* d_out, int out_size) {
    const float* x   = (const float*)d_in[0];
    const int*   ei  = (const int*)  d_in[1];
    const float* W1  = (const float*)d_in[2];
    const float* b1  = (const float*)d_in[3];
    const float* W2  = (const float*)d_in[4];
    const float* b2  = (const float*)d_in[5];
    const float* g1  = (const float*)d_in[6];
    const float* be1 = (const float*)d_in[7];
    const float* m1  = (const float*)d_in[8];
    const float* v1  = (const float*)d_in[9];
    const float* g2  = (const float*)d_in[10];
    const float* be2 = (const float*)d_in[11];
    const float* m2  = (const float*)d_in[12];
    const float* v2  = (const float*)d_in[13];
    const float* fcW = (const float*)d_in[14];
    const float* fcb = (const float*)d_in[15];
    float* out = (float*)d_out;

    int N = in_sizes[0] / 128;
    int E = in_sizes[1] / 2;
    const int* rows = ei;
    const int* cols = ei + E;

    cudaFuncSetAttribute(gemm_mma, cudaFuncAttributeMaxDynamicSharedMemorySize, SM_GT);

    int gblocks = (N + 127) / 128;
    int hblocks = (E + 255) / 256;
    int nb = (N + 1023) / 1024;          // 98 blocks, all co-resident

    prep<<<128 + hblocks, 256>>>(W1, W2, rows, E);                     // 0
    gemm_mma<<<gblocks, 256, SM_GT>>>(0, x, 0, N);                     // 1
    csr_fused<<<nb, 1024>>>(rows, cols, N, E, nb);                     // 2
    aggregate<<<(N + 15) / 16, 256>>>(b1, g1, be1, m1, v1, 1, N);      // 3 <- profiled
    gemm_mma<<<gblocks, 256, SM_GT>>>(1, x, 1, N);                     // 4
    aggregate<<<(N + 15) / 16, 256>>>(b2, g2, be2, m2, v2, 2, N);      // 5
    fc_kernel<<<(N + 31) / 32, 160>>>(x, fcW, fcb, out, N);            // 6
}

// round 14
// speedup vs baseline: 1.9227x; 1.9227x over previous
#include <cuda_runtime.h>
#include <cuda_fp16.h>
#include <cuda_bf16.h>
#include <cstdint>

#define NN 100000
#define EE 1600000
#define HH 128
#define OUTC 40

typedef unsigned long long u64;
typedef unsigned int u32;

// ---------------- static device scratch (allocation-free rule) ----------------
__device__ __half g_h [(size_t)NN * HH];  // xW (layer1 then layer2), fp16 storage
__device__ __half g_x1[(size_t)NN * HH];  // relu(bn1(gcn1)), fp16 storage
__device__ __half g_x2[(size_t)NN * HH];  // relu(bn2(gcn2)), fp16 storage
__device__ float  g_dinv[NN];
__device__ int    g_deg[NN];              // zeroed after consumption each call
__device__ int    g_rowptr[NN + 1];
__device__ int    g_cursor[NN];
__device__ uint2  g_cw[EE];               // packed (col, weight-bits) per edge
__device__ int    g_bsum[128];
// global spin-barrier state (generation-based; monotonic across replays)
__device__ volatile int g_bar_count;
__device__ volatile int g_bar_gen;
// FRAGMENT-MAJOR bf16 hi/lo images of W1/W2 B-operand
__device__ __align__(16) u32 g_Bh1[8192];
__device__ __align__(16) u32 g_Bl1[8192];
__device__ __align__(16) u32 g_Bh2[8192];
__device__ __align__(16) u32 g_Bl2[8192];
// FRAGMENT-MAJOR bf16 hi/lo images of fc_W [384,40]:
// u32 index = ((ktg*5 + nt)*32 + lane)*2 + r,  ktg 0..23, nt 0..4
__device__ __align__(16) u32 g_BhF[7680];
__device__ __align__(16) u32 g_BlF[7680];

// ---------------- mma.sync bf16 (m16n8k16, fp32 accum) ----------------
__device__ __forceinline__ void mma_bf16(float* c, const u32* a, const u32* b) {
    asm volatile(
        "mma.sync.aligned.m16n8k16.row.col.f32.bf16.bf16.f32 "
        "{%0,%1,%2,%3}, {%4,%5,%6,%7}, {%8,%9}, {%0,%1,%2,%3};"
        : "+f"(c[0]), "+f"(c[1]), "+f"(c[2]), "+f"(c[3])
        : "r"(a[0]), "r"(a[1]), "r"(a[2]), "r"(a[3]), "r"(b[0]), "r"(b[1]));
}

// ---------------- bprep body: W[k][n] (row stride 128) -> fragment-major ------------
__device__ __forceinline__ void bprep_body(const float* __restrict__ W, int sel, int i) {
    __nv_bfloat16* bh = (__nv_bfloat16*)(sel ? g_Bh2 : g_Bh1);
    __nv_bfloat16* bl = (__nv_bfloat16*)(sel ? g_Bl2 : g_Bl1);
    int k = i >> 7, n = i & 127;
    float v = W[i];
    __nv_bfloat16 h = __float2bfloat16(v);
    __nv_bfloat16 l = __float2bfloat16(v - __bfloat162float(h));
    int w   = n >> 4;
    int nt  = (n >> 3) & 1;
    int g   = n & 7;
    int kp  = k >> 1;
    int kt  = kp >> 3;
    int kpj = kp & 7;
    int b4  = kpj & 3;
    int reg = kpj >> 2;
    int lane = g * 4 + b4;
    int idx = (((w * 8 + kt) * 32 + lane) * 4 + nt * 2 + reg) * 2 + (k & 1);
    bh[idx] = h;
    bl[idx] = l;
}

// fc_W [384,40] row-major -> fragment-major bf16 hi/lo
__device__ __forceinline__ void bprep_fc(const float* __restrict__ W, int i) {
    __nv_bfloat16* bh = (__nv_bfloat16*)g_BhF;
    __nv_bfloat16* bl = (__nv_bfloat16*)g_BlF;
    int k = i / 40, n = i % 40;
    float v = W[i];
    __nv_bfloat16 h = __float2bfloat16(v);
    __nv_bfloat16 l = __float2bfloat16(v - __bfloat162float(h));
    int nt = n >> 3;
    int g  = n & 7;
    int kt = k >> 4;
    int kk = k & 15;
    int hf = kk & 1;
    int b4 = (kk & 7) >> 1;
    int r  = kk >> 3;
    int lane = g * 4 + b4;
    int idx = (((kt * 5 + nt) * 32 + lane) * 2 + r) * 2 + hf;
    bh[idx] = h;
    bl[idx] = l;
}

// ---------------- prep: bprep(W1,W2,fcW) + histo, merged by block range --------
__global__ void prep(const float* __restrict__ W1, const float* __restrict__ W2,
                     const float* __restrict__ fcW,
                     const int* __restrict__ rows, int e) {
    int b = blockIdx.x;
    if (b < 64) {
        bprep_body(W1, 0, b * 256 + threadIdx.x);
    } else if (b < 128) {
        bprep_body(W2, 1, (b - 64) * 256 + threadIdx.x);
    } else if (b < 188) {
        bprep_fc(fcW, (b - 128) * 256 + threadIdx.x);   // 60*256 = 15360 exactly
    } else {
        int i = (b - 188) * 256 + threadIdx.x;
        if (i < e) atomicAdd(&g_deg[rows[i]], 1);
    }
}

// ---------------- fused CSR build (scan + offsets + scatter, one launch) -----------
__device__ __forceinline__ void grid_bar(int nblocks) {
    __syncthreads();
    if (threadIdx.x == 0) {
        int gen = g_bar_gen;
        __threadfence();
        if (atomicAdd((int*)&g_bar_count, 1) == nblocks - 1) {
            g_bar_count = 0;
            __threadfence();
            g_bar_gen = gen + 1;
        } else {
            while (g_bar_gen == gen) { }
            __threadfence();
        }
    }
    __syncthreads();
}

__global__ __launch_bounds__(1024) void csr_fused(const int* __restrict__ rows,
                                                  const int* __restrict__ cols,
                                                  int n, int e, int nblocks) {
    __shared__ int s[1024];
    __shared__ int s2[128];
    int b = blockIdx.x;
    int t = threadIdx.x;
    int i = b * 1024 + t;

    int v = (i < n) ? g_deg[i] : 0;
    s[t] = v;
    __syncthreads();
    for (int off = 1; off < 1024; off <<= 1) {
        int u = (t >= off) ? s[t - off] : 0;
        __syncthreads();
        s[t] += u;
        __syncthreads();
    }
    if (i < n) g_rowptr[i] = s[t] - v;
    if (t == 1023) g_bsum[b] = s[1023];

    grid_bar(nblocks);

    if (t < 128) s2[t] = (t < nblocks) ? g_bsum[t] : 0;
    __syncthreads();
    for (int off = 1; off < 128; off <<= 1) {
        int u = (t < 128 && t >= off) ? s2[t - off] : 0;
        __syncthreads();
        if (t < 128) s2[t] += u;
        __syncthreads();
    }
    if (i < n) {
        int pre = (b == 0) ? 0 : s2[b - 1];
        int val = g_rowptr[i] + pre;
        g_rowptr[i] = val;
        g_cursor[i] = val;
        g_dinv[i]   = rsqrtf((float)v + 1.0f);
        g_deg[i]    = 0;
    }
    if (i == 0) g_rowptr[n] = e;

    grid_bar(nblocks);

    int stride = nblocks * 1024;
    for (int jj = b * 1024 + t; jj < e; jj += stride) {
        int r = rows[jj];
        int c = cols[jj];
        int p = atomicAdd(&g_cursor[r], 1);
        g_cw[p] = make_uint2((u32)c, __float_as_uint(g_dinv[r] * g_dinv[c]));
    }
}

// ---------------- tensor GEMM: g_h[M,128](fp16) = A[M,128] @ W ----------------
#define SM_GT 65536

__global__ __launch_bounds__(256) void gemm_mma(int a_sel, const float* __restrict__ Aext,
                                                int b_sel, int M, int moff) {
    extern __shared__ u32 sm[];
    u32* sAh = sm;
    u32* sAl = sm + 8192;

    const uint4* __restrict__ B4h = (const uint4*)(b_sel ? g_Bh2 : g_Bh1);
    const uint4* __restrict__ B4l = (const uint4*)(b_sel ? g_Bl2 : g_Bl1);

    int tid = threadIdx.x;
    int bm  = (blockIdx.x + moff) * 128;

    for (int i = tid; i < 8192; i += 256) {
        int row = i >> 6, kpair = i & 63;
        int gm = bm + row; if (gm >= M) gm = M - 1;
        float2 v;
        if (a_sel) {
            __half2 hv = *(const __half2*)&g_x1[(size_t)gm * 128 + 2 * kpair];
            v = __half22float2(hv);
        } else {
            v = *(const float2*)&Aext[(size_t)gm * 128 + 2 * kpair];
        }
        __nv_bfloat16 hx = __float2bfloat16(v.x);
        __nv_bfloat16 hy = __float2bfloat16(v.y);
        __nv_bfloat16 lx = __float2bfloat16(v.x - __bfloat162float(hx));
        __nv_bfloat16 ly = __float2bfloat16(v.y - __bfloat162float(hy));
        int mt = row >> 4;
        int r  = row & 15;
        int g  = r & 7;
        int kt  = kpair >> 3;
        int kpj = kpair & 7;
        int b4  = kpj & 3;
        int reg = (r >> 3) | ((kpj >> 2) << 1);
        int lane = g * 4 + b4;
        int idx = ((mt * 8 + kt) * 32 + lane) * 4 + reg;
        __nv_bfloat162 ph = __halves2bfloat162(hx, hy);
        __nv_bfloat162 pl = __halves2bfloat162(lx, ly);
        sAh[idx] = *(u32*)&ph;
        sAl[idx] = *(u32*)&pl;
    }
    __syncthreads();

    int w = tid >> 5;
    int l = tid & 31;
    int g  = l >> 2;
    int b4 = l & 3;
    int nbase = w * 16;

    float c[8][2][4];
#pragma unroll
    for (int mt = 0; mt < 8; mt++)
#pragma unroll
        for (int nt = 0; nt < 2; nt++)
#pragma unroll
            for (int q = 0; q < 4; q++) c[mt][nt][q] = 0.f;

#pragma unroll
    for (int kt = 0; kt < 8; kt++) {
        int bidx = (w * 8 + kt) * 32 + l;
        uint4 bhv = B4h[bidx];
        uint4 blv = B4l[bidx];
        u32 bh0[2] = {bhv.x, bhv.y};
        u32 bh1[2] = {bhv.z, bhv.w};
        u32 bl0[2] = {blv.x, blv.y};
        u32 bl1[2] = {blv.z, blv.w};
#pragma unroll
        for (int mt = 0; mt < 8; mt++) {
            int aidx = ((mt * 8 + kt) * 32 + l) * 4;
            uint4 ahv = *(const uint4*)&sAh[aidx];
            uint4 alv = *(const uint4*)&sAl[aidx];
            u32 ah[4] = {ahv.x, ahv.y, ahv.z, ahv.w};
            u32 al[4] = {alv.x, alv.y, alv.z, alv.w};
            mma_bf16(c[mt][0], ah, bh0);
            mma_bf16(c[mt][0], al, bh0);
            mma_bf16(c[mt][0], ah, bl0);
            mma_bf16(c[mt][1], ah, bh1);
            mma_bf16(c[mt][1], al, bh1);
            mma_bf16(c[mt][1], ah, bl1);
        }
    }

#pragma unroll
    for (int mt = 0; mt < 8; mt++) {
        int gm0 = bm + mt * 16 + g;
        int gm1 = gm0 + 8;
#pragma unroll
        for (int nt = 0; nt < 2; nt++) {
            int col = nbase + nt * 8 + b4 * 2;
            if (gm0 < M)
                *(__half2*)&g_h[(size_t)gm0 * 128 + col] = __floats2half2_rn(c[mt][nt][0], c[mt][nt][1]);
            if (gm1 < M)
                *(__half2*)&g_h[(size_t)gm1 * 128 + col] = __floats2half2_rn(c[mt][nt][2], c[mt][nt][3]);
        }
    }
}

// ---------------- gather aggregation + bias + BN + ReLU ----------------
__device__ __forceinline__ void acc_edge(float* acc, uint4 r, float w) {
#pragma unroll
    for (int q = 0; q < 4; q++) {
        float2 f = __half22float2(((const __half2*)&r)[q]);
        acc[2 * q]     += f.x * w;
        acc[2 * q + 1] += f.y * w;
    }
}

__global__ __launch_bounds__(256) void aggregate(const float* __restrict__ bias,
                          const float* __restrict__ gamma,
                          const float* __restrict__ beta,
                          const float* __restrict__ mean,
                          const float* __restrict__ var,
                          int dst_sel, int n) {
    int node = (blockIdx.x * blockDim.x + threadIdx.x) >> 4;
    if (node >= n) return;
    int lane = threadIdx.x & 15;
    int c0   = lane << 3;

    float di    = g_dinv[node];
    int   start = g_rowptr[node];
    int   end   = g_rowptr[node + 1];

    float acc[8];
#pragma unroll
    for (int q = 0; q < 8; q++) acc[q] = 0.f;

    int j = start;
    for (; j + 7 < end; j += 8) {
        uint2 e0 = g_cw[j + 0], e1 = g_cw[j + 1], e2 = g_cw[j + 2], e3 = g_cw[j + 3];
        uint2 e4 = g_cw[j + 4], e5 = g_cw[j + 5], e6 = g_cw[j + 6], e7 = g_cw[j + 7];
        uint4 r0 = *(const uint4*)&g_h[(size_t)e0.x * 128 + c0];
        uint4 r1 = *(const uint4*)&g_h[(size_t)e1.x * 128 + c0];
        uint4 r2 = *(const uint4*)&g_h[(size_t)e2.x * 128 + c0];
        uint4 r3 = *(const uint4*)&g_h[(size_t)e3.x * 128 + c0];
        uint4 r4 = *(const uint4*)&g_h[(size_t)e4.x * 128 + c0];
        uint4 r5 = *(const uint4*)&g_h[(size_t)e5.x * 128 + c0];
        uint4 r6 = *(const uint4*)&g_h[(size_t)e6.x * 128 + c0];
        uint4 r7 = *(const uint4*)&g_h[(size_t)e7.x * 128 + c0];
        acc_edge(acc, r0, __uint_as_float(e0.y));
        acc_edge(acc, r1, __uint_as_float(e1.y));
        acc_edge(acc, r2, __uint_as_float(e2.y));
        acc_edge(acc, r3, __uint_as_float(e3.y));
        acc_edge(acc, r4, __uint_as_float(e4.y));
        acc_edge(acc, r5, __uint_as_float(e5.y));
        acc_edge(acc, r6, __uint_as_float(e6.y));
        acc_edge(acc, r7, __uint_as_float(e7.y));
    }
    for (; j + 3 < end; j += 4) {
        uint2 e0 = g_cw[j + 0], e1 = g_cw[j + 1], e2 = g_cw[j + 2], e3 = g_cw[j + 3];
        uint4 r0 = *(const uint4*)&g_h[(size_t)e0.x * 128 + c0];
        uint4 r1 = *(const uint4*)&g_h[(size_t)e1.x * 128 + c0];
        uint4 r2 = *(const uint4*)&g_h[(size_t)e2.x * 128 + c0];
        uint4 r3 = *(const uint4*)&g_h[(size_t)e3.x * 128 + c0];
        acc_edge(acc, r0, __uint_as_float(e0.y));
        acc_edge(acc, r1, __uint_as_float(e1.y));
        acc_edge(acc, r2, __uint_as_float(e2.y));
        acc_edge(acc, r3, __uint_as_float(e3.y));
    }
    for (; j < end; j++) {
        uint2 e0 = g_cw[j];
        uint4 r0 = *(const uint4*)&g_h[(size_t)e0.x * 128 + c0];
        acc_edge(acc, r0, __uint_as_float(e0.y));
    }
    {
        uint4 rs = *(const uint4*)&g_h[(size_t)node * 128 + c0];
        acc_edge(acc, rs, di * di);
    }

    __half* __restrict__ out = (dst_sel == 1) ? g_x1 : g_x2;
    union { __half2 h2[4]; uint4 v; } pk;
#pragma unroll
    for (int h = 0; h < 2; h++) {
        int c = c0 + h * 4;
        float4 bb = *(const float4*)&bias[c];
        float4 gg = *(const float4*)&gamma[c];
        float4 be = *(const float4*)&beta[c];
        float4 mm = *(const float4*)&mean[c];
        float4 vv = *(const float4*)&var[c];
        float s0 = gg.x * rsqrtf(vv.x + 1e-5f);
        float s1 = gg.y * rsqrtf(vv.y + 1e-5f);
        float s2 = gg.z * rsqrtf(vv.z + 1e-5f);
        float s3 = gg.w * rsqrtf(vv.w + 1e-5f);
        float y0 = fmaxf((acc[4 * h + 0] + bb.x - mm.x) * s0 + be.x, 0.0f);
        float y1 = fmaxf((acc[4 * h + 1] + bb.y - mm.y) * s1 + be.y, 0.0f);
        float y2 = fmaxf((acc[4 * h + 2] + bb.z - mm.z) * s2 + be.z, 0.0f);
        float y3 = fmaxf((acc[4 * h + 3] + bb.w - mm.w) * s3 + be.w, 0.0f);
        pk.h2[2 * h]     = __floats2half2_rn(y0, y1);
        pk.h2[2 * h + 1] = __floats2half2_rn(y2, y3);
    }
    *(uint4*)&out[(size_t)node * 128 + c0] = pk.v;
}

// ---------------- fc via tensor cores: out[N,40] = [x0|x1|x2] @ fc_W + fc_b --------
// block = 256 thr / 8 warps / 128 rows; warp w owns rows [w*16, w*16+16), all 40 cols.
// K = 3 chunks of 128 (x0 fp32, x1 fp16, x2 fp16), staged fragment-major like gemm.
__global__ __launch_bounds__(256) void fc_mma(const float* __restrict__ x0,
                                              const float* __restrict__ bias,
                                              float* __restrict__ out, int M) {
    extern __shared__ u32 sm[];
    u32* sAh = sm;
    u32* sAl = sm + 8192;

    int tid = threadIdx.x;
    int bm  = blockIdx.x * 128;
    int w = tid >> 5;
    int l = tid & 31;
    int g  = l >> 2;
    int b4 = l & 3;

    // accumulators: 5 n-tiles x 4 regs, init with bias (col-dependent only)
    float c[5][4];
#pragma unroll
    for (int nt = 0; nt < 5; nt++) {
        float bv0 = bias[nt * 8 + b4 * 2];
        float bv1 = bias[nt * 8 + b4 * 2 + 1];
        c[nt][0] = bv0; c[nt][1] = bv1; c[nt][2] = bv0; c[nt][3] = bv1;
    }

    for (int s = 0; s < 3; s++) {
        if (s) __syncthreads();
        // stage chunk s fragment-major (identical mapping to gemm_mma)
        for (int i = tid; i < 8192; i += 256) {
            int row = i >> 6, kpair = i & 63;
            int gm = bm + row; if (gm >= M) gm = M - 1;
            float2 v;
            if (s == 0) {
                v = *(const float2*)&x0[(size_t)gm * 128 + 2 * kpair];
            } else {
                const __half* S = (s == 1) ? g_x1 : g_x2;
                __half2 hv = *(const __half2*)&S[(size_t)gm * 128 + 2 * kpair];
                v = __half22float2(hv);
            }
            __nv_bfloat16 hx = __float2bfloat16(v.x);
            __nv_bfloat16 hy = __float2bfloat16(v.y);
            __nv_bfloat16 lx = __float2bfloat16(v.x - __bfloat162float(hx));
            __nv_bfloat16 ly = __float2bfloat16(v.y - __bfloat162float(hy));
            int mt = row >> 4;
            int r  = row & 15;
            int gg = r & 7;
            int kt  = kpair >> 3;
            int kpj = kpair & 7;
            int bb  = kpj & 3;
            int reg = (r >> 3) | ((kpj >> 2) << 1);
            int lane = gg * 4 + bb;
            int idx = ((mt * 8 + kt) * 32 + lane) * 4 + reg;
            __nv_bfloat162 ph = __halves2bfloat162(hx, hy);
            __nv_bfloat162 pl = __halves2bfloat162(lx, ly);
            sAh[idx] = *(u32*)&ph;
            sAl[idx] = *(u32*)&pl;
        }
        __syncthreads();

#pragma unroll
        for (int kt = 0; kt < 8; kt++) {
            int ktg = s * 8 + kt;
            // A fragment for this warp's m-tile (mt = w)
            int aidx = ((w * 8 + kt) * 32 + l) * 4;
            uint4 ahv = *(const uint4*)&sAh[aidx];
            uint4 alv = *(const uint4*)&sAl[aidx];
            u32 ah[4] = {ahv.x, ahv.y, ahv.z, ahv.w};
            u32 al[4] = {alv.x, alv.y, alv.z, alv.w};
#pragma unroll
            for (int nt = 0; nt < 5; nt++) {
                int bidx = ((ktg * 5 + nt) * 32 + l);
                uint2 bh = *(const uint2*)&g_BhF[bidx * 2];
                uint2 bl = *(const uint2*)&g_BlF[bidx * 2];
                u32 bhv[2] = {bh.x, bh.y};
                u32 blv[2] = {bl.x, bl.y};
                mma_bf16(c[nt], ah, bhv);
                mma_bf16(c[nt], al, bhv);
                mma_bf16(c[nt], ah, blv);
            }
        }
    }

    // epilogue: rows bm + w*16 + g (+8), cols nt*8 + b4*2 (+1)
    int gm0 = bm + w * 16 + g;
    int gm1 = gm0 + 8;
#pragma unroll
    for (int nt = 0; nt < 5; nt++) {
        int col = nt * 8 + b4 * 2;
        if (gm0 < M) *(float2*)&out[(size_t)gm0 * 40 + col] = make_float2(c[nt][0], c[nt][1]);
        if (gm1 < M) *(float2*)&out[(size_t)gm1 * 40 + col] = make_float2(c[nt][2], c[nt][3]);
    }
}

// ---------------- launch ----------------
extern "C" void kernel_launch(void* const* d_in, const int* in_sizes, int n_in,
                              void* d_out, int out_size) {
    const float* x   = (const float*)d_in[0];
    const int*   ei  = (const int*)  d_in[1];
    const float* W1  = (const float*)d_in[2];
    const float* b1  = (const float*)d_in[3];
    const float* W2  = (const float*)d_in[4];
    const float* b2  = (const float*)d_in[5];
    const float* g1  = (const float*)d_in[6];
    const float* be1 = (const float*)d_in[7];
    const float* m1  = (const float*)d_in[8];
    const float* v1  = (const float*)d_in[9];
    const float* g2  = (const float*)d_in[10];
    const float* be2 = (const float*)d_in[11];
    const float* m2  = (const float*)d_in[12];
    const float* v2  = (const float*)d_in[13];
    const float* fcW = (const float*)d_in[14];
    const float* fcb = (const float*)d_in[15];
    float* out = (float*)d_out;

    int N = in_sizes[0] / 128;
    int E = in_sizes[1] / 2;
    const int* rows = ei;
    const int* cols = ei + E;

    cudaFuncSetAttribute(gemm_mma, cudaFuncAttributeMaxDynamicSharedMemorySize, SM_GT);
    cudaFuncSetAttribute(fc_mma,   cudaFuncAttributeMaxDynamicSharedMemorySize, SM_GT);

    int gblocks = (N + 127) / 128;           // 782
    int ga = gblocks / 2;                    // 391
    int gb = gblocks - ga;                   // 391
    int hblocks = (E + 255) / 256;           // 6250
    int nb = (N + 1023) / 1024;              // 98

    prep<<<188 + hblocks, 256>>>(W1, W2, fcW, rows, E);                // 0
    gemm_mma<<<ga, 256, SM_GT>>>(0, x, 0, N, 0);                       // 1
    gemm_mma<<<gb, 256, SM_GT>>>(0, x, 0, N, ga);                      // 2
    csr_fused<<<nb, 1024>>>(rows, cols, N, E, nb);                     // 3 <- profiled
    aggregate<<<(N + 15) / 16, 256>>>(b1, g1, be1, m1, v1, 1, N);      // 4
    gemm_mma<<<gblocks, 256, SM_GT>>>(1, x, 1, N, 0);                  // 5
    aggregate<<<(N + 15) / 16, 256>>>(b2, g2, be2, m2, v2, 2, N);      // 6
    fc_mma<<<gblocks, 256, SM_GT>>>(x, fcb, out, N);                   // 7
}

// round 15
// speedup vs baseline: 1.9744x; 1.0269x over previous
#include <cuda_runtime.h>
#include <cuda_fp16.h>
#include <cuda_bf16.h>
#include <cstdint>

#define NN 100000
#define EE 1600000
#define HH 128
#define OUTC 40

typedef unsigned long long u64;
typedef unsigned int u32;

// ---------------- static device scratch (allocation-free rule) ----------------
__device__ __half g_h [(size_t)NN * HH];  // xW (layer1 then layer2), fp16 storage
__device__ __half g_x1[(size_t)NN * HH];  // relu(bn1(gcn1)), fp16 storage
__device__ __half g_x2[(size_t)NN * HH];  // relu(bn2(gcn2)), fp16 storage
__device__ float  g_dinv[NN];
__device__ int    g_deg[NN];              // zeroed after consumption each call
__device__ int    g_rowptr[NN + 1];
__device__ int    g_cursor[NN];
__device__ uint2  g_cw[EE];               // packed (col, weight-bits) per edge
__device__ int    g_bsum[128];
// global spin-barrier state (generation-based; monotonic across replays)
__device__ volatile int g_bar_count;
__device__ volatile int g_bar_gen;
// FRAGMENT-MAJOR bf16 hi/lo images of W1/W2 B-operand
__device__ __align__(16) u32 g_Bh1[8192];
__device__ __align__(16) u32 g_Bl1[8192];
__device__ __align__(16) u32 g_Bh2[8192];
__device__ __align__(16) u32 g_Bl2[8192];
// FRAGMENT-MAJOR bf16 hi/lo images of fc_W [384,40]
__device__ __align__(16) u32 g_BhF[7680];
__device__ __align__(16) u32 g_BlF[7680];

// ---------------- mma.sync bf16 (m16n8k16, fp32 accum) ----------------
__device__ __forceinline__ void mma_bf16(float* c, const u32* a, const u32* b) {
    asm volatile(
        "mma.sync.aligned.m16n8k16.row.col.f32.bf16.bf16.f32 "
        "{%0,%1,%2,%3}, {%4,%5,%6,%7}, {%8,%9}, {%0,%1,%2,%3};"
        : "+f"(c[0]), "+f"(c[1]), "+f"(c[2]), "+f"(c[3])
        : "r"(a[0]), "r"(a[1]), "r"(a[2]), "r"(a[3]), "r"(b[0]), "r"(b[1]));
}

// ---------------- bprep body: W[k][n] (row stride 128) -> fragment-major ------------
__device__ __forceinline__ void bprep_body(const float* __restrict__ W, int sel, int i) {
    __nv_bfloat16* bh = (__nv_bfloat16*)(sel ? g_Bh2 : g_Bh1);
    __nv_bfloat16* bl = (__nv_bfloat16*)(sel ? g_Bl2 : g_Bl1);
    int k = i >> 7, n = i & 127;
    float v = W[i];
    __nv_bfloat16 h = __float2bfloat16(v);
    __nv_bfloat16 l = __float2bfloat16(v - __bfloat162float(h));
    int w   = n >> 4;
    int nt  = (n >> 3) & 1;
    int g   = n & 7;
    int kp  = k >> 1;
    int kt  = kp >> 3;
    int kpj = kp & 7;
    int b4  = kpj & 3;
    int reg = kpj >> 2;
    int lane = g * 4 + b4;
    int idx = (((w * 8 + kt) * 32 + lane) * 4 + nt * 2 + reg) * 2 + (k & 1);
    bh[idx] = h;
    bl[idx] = l;
}

// fc_W [384,40] row-major -> fragment-major bf16 hi/lo
__device__ __forceinline__ void bprep_fc(const float* __restrict__ W, int i) {
    __nv_bfloat16* bh = (__nv_bfloat16*)g_BhF;
    __nv_bfloat16* bl = (__nv_bfloat16*)g_BlF;
    int k = i / 40, n = i % 40;
    float v = W[i];
    __nv_bfloat16 h = __float2bfloat16(v);
    __nv_bfloat16 l = __float2bfloat16(v - __bfloat162float(h));
    int nt = n >> 3;
    int g  = n & 7;
    int kt = k >> 4;
    int kk = k & 15;
    int hf = kk & 1;
    int b4 = (kk & 7) >> 1;
    int r  = kk >> 3;
    int lane = g * 4 + b4;
    int idx = (((kt * 5 + nt) * 32 + lane) * 2 + r) * 2 + hf;
    bh[idx] = h;
    bl[idx] = l;
}

// ---------------- prep: bprep(W1,W2,fcW) + histo, merged by block range --------
__global__ void prep(const float* __restrict__ W1, const float* __restrict__ W2,
                     const float* __restrict__ fcW,
                     const int* __restrict__ rows, int e) {
    int b = blockIdx.x;
    if (b < 64) {
        bprep_body(W1, 0, b * 256 + threadIdx.x);
    } else if (b < 128) {
        bprep_body(W2, 1, (b - 64) * 256 + threadIdx.x);
    } else if (b < 188) {
        bprep_fc(fcW, (b - 128) * 256 + threadIdx.x);   // 60*256 = 15360 exactly
    } else {
        int i = (b - 188) * 256 + threadIdx.x;
        if (i < e) atomicAdd(&g_deg[rows[i]], 1);
    }
}

// ---------------- fused CSR build (scan + offsets + scatter, one launch) -----------
__device__ __forceinline__ void grid_bar(int nblocks) {
    __syncthreads();
    if (threadIdx.x == 0) {
        int gen = g_bar_gen;
        __threadfence();
        if (atomicAdd((int*)&g_bar_count, 1) == nblocks - 1) {
            g_bar_count = 0;
            __threadfence();
            g_bar_gen = gen + 1;
        } else {
            while (g_bar_gen == gen) { }
            __threadfence();
        }
    }
    __syncthreads();
}

__device__ __forceinline__ int warp_iscan(int v, int lane) {
#pragma unroll
    for (int off = 1; off < 32; off <<= 1) {
        int u = __shfl_up_sync(0xffffffffu, v, off);
        if (lane >= off) v += u;
    }
    return v;
}

__global__ __launch_bounds__(1024) void csr_fused(const int* __restrict__ rows,
                                                  const int* __restrict__ cols,
                                                  int n, int e, int nblocks) {
    __shared__ int swsum[32];     // per-warp totals
    __shared__ int s2[128];       // block-total inclusive scan
    int b = blockIdx.x;
    int t = threadIdx.x;
    int lane = t & 31;
    int wid  = t >> 5;
    int i = b * 1024 + t;

    // phase 1: block scan of degrees via warp shuffles (2 barriers total)
    int v = (i < n) ? g_deg[i] : 0;
    int incl = warp_iscan(v, lane);
    if (lane == 31) swsum[wid] = incl;
    __syncthreads();
    if (wid == 0) {
        int wv = swsum[lane];
        int wi = warp_iscan(wv, lane);
        swsum[lane] = wi - wv;    // exclusive warp offset
    }
    __syncthreads();
    int block_incl = incl + swsum[wid];
    if (i < n) g_rowptr[i] = block_incl - v;    // block-local exclusive
    if (t == 1023) g_bsum[b] = block_incl;      // block total

    grid_bar(nblocks);

    // phase 2: scan <=128 block totals (warp 0, 4 chunks of 32 with carry)
    if (wid == 0) {
        int carry = 0;
#pragma unroll
        for (int ch = 0; ch < 4; ch++) {
            int idx = ch * 32 + lane;
            int bv = (idx < nblocks) ? g_bsum[idx] : 0;
            int bi = warp_iscan(bv, lane) + carry;
            s2[idx] = bi;                        // inclusive
            carry = __shfl_sync(0xffffffffu, bi, 31);
        }
    }
    __syncthreads();
    if (i < n) {
        int pre = (b == 0) ? 0 : s2[b - 1];
        int val = (block_incl - v) + pre;
        g_rowptr[i] = val;
        g_cursor[i] = val;
        g_dinv[i]   = rsqrtf((float)v + 1.0f);
        g_deg[i]    = 0;
    }
    if (i == 0) g_rowptr[n] = e;

    grid_bar(nblocks);

    // phase 3: scatter edges, 4-deep batched for MLP on the atomic path
    int stride = nblocks * 1024;
    for (int j0 = b * 1024 + t; j0 < e; j0 += 4 * stride) {
        int  r[4], c[4];
        bool m[4];
#pragma unroll
        for (int q = 0; q < 4; q++) {
            int idx = j0 + q * stride;
            m[q] = (idx < e);
            if (m[q]) { r[q] = rows[idx]; c[q] = cols[idx]; }
        }
        float dr[4], dc[4];
#pragma unroll
        for (int q = 0; q < 4; q++)
            if (m[q]) { dr[q] = g_dinv[r[q]]; dc[q] = g_dinv[c[q]]; }
#pragma unroll
        for (int q = 0; q < 4; q++)
            if (m[q]) {
                int p = atomicAdd(&g_cursor[r[q]], 1);
                g_cw[p] = make_uint2((u32)c[q], __float_as_uint(dr[q] * dc[q]));
            }
    }
}

// ---------------- tensor GEMM: g_h[M,128](fp16) = A[M,128] @ W ----------------
#define SM_GT 65536

__global__ __launch_bounds__(256) void gemm_mma(int a_sel, const float* __restrict__ Aext,
                                                int b_sel, int M) {
    extern __shared__ u32 sm[];
    u32* sAh = sm;
    u32* sAl = sm + 8192;

    const uint4* __restrict__ B4h = (const uint4*)(b_sel ? g_Bh2 : g_Bh1);
    const uint4* __restrict__ B4l = (const uint4*)(b_sel ? g_Bl2 : g_Bl1);

    int tid = threadIdx.x;
    int bm  = blockIdx.x * 128;

    for (int i = tid; i < 8192; i += 256) {
        int row = i >> 6, kpair = i & 63;
        int gm = bm + row; if (gm >= M) gm = M - 1;
        float2 v;
        if (a_sel) {
            __half2 hv = *(const __half2*)&g_x1[(size_t)gm * 128 + 2 * kpair];
            v = __half22float2(hv);
        } else {
            v = *(const float2*)&Aext[(size_t)gm * 128 + 2 * kpair];
        }
        __nv_bfloat16 hx = __float2bfloat16(v.x);
        __nv_bfloat16 hy = __float2bfloat16(v.y);
        __nv_bfloat16 lx = __float2bfloat16(v.x - __bfloat162float(hx));
        __nv_bfloat16 ly = __float2bfloat16(v.y - __bfloat162float(hy));
        int mt = row >> 4;
        int r  = row & 15;
        int g  = r & 7;
        int kt  = kpair >> 3;
        int kpj = kpair & 7;
        int b4  = kpj & 3;
        int reg = (r >> 3) | ((kpj >> 2) << 1);
        int lane = g * 4 + b4;
        int idx = ((mt * 8 + kt) * 32 + lane) * 4 + reg;
        __nv_bfloat162 ph = __halves2bfloat162(hx, hy);
        __nv_bfloat162 pl = __halves2bfloat162(lx, ly);
        sAh[idx] = *(u32*)&ph;
        sAl[idx] = *(u32*)&pl;
    }
    __syncthreads();

    int w = tid >> 5;
    int l = tid & 31;
    int g  = l >> 2;
    int b4 = l & 3;
    int nbase = w * 16;

    float c[8][2][4];
#pragma unroll
    for (int mt = 0; mt < 8; mt++)
#pragma unroll
        for (int nt = 0; nt < 2; nt++)
#pragma unroll
            for (int q = 0; q < 4; q++) c[mt][nt][q] = 0.f;

#pragma unroll
    for (int kt = 0; kt < 8; kt++) {
        int bidx = (w * 8 + kt) * 32 + l;
        uint4 bhv = B4h[bidx];
        uint4 blv = B4l[bidx];
        u32 bh0[2] = {bhv.x, bhv.y};
        u32 bh1[2] = {bhv.z, bhv.w};
        u32 bl0[2] = {blv.x, blv.y};
        u32 bl1[2] = {blv.z, blv.w};
#pragma unroll
        for (int mt = 0; mt < 8; mt++) {
            int aidx = ((mt * 8 + kt) * 32 + l) * 4;
            uint4 ahv = *(const uint4*)&sAh[aidx];
            uint4 alv = *(const uint4*)&sAl[aidx];
            u32 ah[4] = {ahv.x, ahv.y, ahv.z, ahv.w};
            u32 al[4] = {alv.x, alv.y, alv.z, alv.w};
            mma_bf16(c[mt][0], ah, bh0);
            mma_bf16(c[mt][0], al, bh0);
            mma_bf16(c[mt][0], ah, bl0);
            mma_bf16(c[mt][1], ah, bh1);
            mma_bf16(c[mt][1], al, bh1);
            mma_bf16(c[mt][1], ah, bl1);
        }
    }

#pragma unroll
    for (int mt = 0; mt < 8; mt++) {
        int gm0 = bm + mt * 16 + g;
        int gm1 = gm0 + 8;
#pragma unroll
        for (int nt = 0; nt < 2; nt++) {
            int col = nbase + nt * 8 + b4 * 2;
            if (gm0 < M)
                *(__half2*)&g_h[(size_t)gm0 * 128 + col] = __floats2half2_rn(c[mt][nt][0], c[mt][nt][1]);
            if (gm1 < M)
                *(__half2*)&g_h[(size_t)gm1 * 128 + col] = __floats2half2_rn(c[mt][nt][2], c[mt][nt][3]);
        }
    }
}

// ---------------- gather aggregation + bias + BN + ReLU ----------------
__device__ __forceinline__ void acc_edge(float* acc, uint4 r, float w) {
#pragma unroll
    for (int q = 0; q < 4; q++) {
        float2 f = __half22float2(((const __half2*)&r)[q]);
        acc[2 * q]     += f.x * w;
        acc[2 * q + 1] += f.y * w;
    }
}

__global__ __launch_bounds__(256) void aggregate(const float* __restrict__ bias,
                          const float* __restrict__ gamma,
                          const float* __restrict__ beta,
                          const float* __restrict__ mean,
                          const float* __restrict__ var,
                          int dst_sel, int n) {
    int node = (blockIdx.x * blockDim.x + threadIdx.x) >> 4;
    if (node >= n) return;
    int lane = threadIdx.x & 15;
    int c0   = lane << 3;

    float di    = g_dinv[node];
    int   start = g_rowptr[node];
    int   end   = g_rowptr[node + 1];

    float acc[8];
#pragma unroll
    for (int q = 0; q < 8; q++) acc[q] = 0.f;

    int j = start;
    for (; j + 7 < end; j += 8) {
        uint2 e0 = g_cw[j + 0], e1 = g_cw[j + 1], e2 = g_cw[j + 2], e3 = g_cw[j + 3];
        uint2 e4 = g_cw[j + 4], e5 = g_cw[j + 5], e6 = g_cw[j + 6], e7 = g_cw[j + 7];
        uint4 r0 = *(const uint4*)&g_h[(size_t)e0.x * 128 + c0];
        uint4 r1 = *(const uint4*)&g_h[(size_t)e1.x * 128 + c0];
        uint4 r2 = *(const uint4*)&g_h[(size_t)e2.x * 128 + c0];
        uint4 r3 = *(const uint4*)&g_h[(size_t)e3.x * 128 + c0];
        uint4 r4 = *(const uint4*)&g_h[(size_t)e4.x * 128 + c0];
        uint4 r5 = *(const uint4*)&g_h[(size_t)e5.x * 128 + c0];
        uint4 r6 = *(const uint4*)&g_h[(size_t)e6.x * 128 + c0];
        uint4 r7 = *(const uint4*)&g_h[(size_t)e7.x * 128 + c0];
        acc_edge(acc, r0, __uint_as_float(e0.y));
        acc_edge(acc, r1, __uint_as_float(e1.y));
        acc_edge(acc, r2, __uint_as_float(e2.y));
        acc_edge(acc, r3, __uint_as_float(e3.y));
        acc_edge(acc, r4, __uint_as_float(e4.y));
        acc_edge(acc, r5, __uint_as_float(e5.y));
        acc_edge(acc, r6, __uint_as_float(e6.y));
        acc_edge(acc, r7, __uint_as_float(e7.y));
    }
    for (; j + 3 < end; j += 4) {
        uint2 e0 = g_cw[j + 0], e1 = g_cw[j + 1], e2 = g_cw[j + 2], e3 = g_cw[j + 3];
        uint4 r0 = *(const uint4*)&g_h[(size_t)e0.x * 128 + c0];
        uint4 r1 = *(const uint4*)&g_h[(size_t)e1.x * 128 + c0];
        uint4 r2 = *(const uint4*)&g_h[(size_t)e2.x * 128 + c0];
        uint4 r3 = *(const uint4*)&g_h[(size_t)e3.x * 128 + c0];
        acc_edge(acc, r0, __uint_as_float(e0.y));
        acc_edge(acc, r1, __uint_as_float(e1.y));
        acc_edge(acc, r2, __uint_as_float(e2.y));
        acc_edge(acc, r3, __uint_as_float(e3.y));
    }
    for (; j < end; j++) {
        uint2 e0 = g_cw[j];
        uint4 r0 = *(const uint4*)&g_h[(size_t)e0.x * 128 + c0];
        acc_edge(acc, r0, __uint_as_float(e0.y));
    }
    {
        uint4 rs = *(const uint4*)&g_h[(size_t)node * 128 + c0];
        acc_edge(acc, rs, di * di);
    }

    __half* __restrict__ out = (dst_sel == 1) ? g_x1 : g_x2;
    union { __half2 h2[4]; uint4 v; } pk;
#pragma unroll
    for (int h = 0; h < 2; h++) {
        int c = c0 + h * 4;
        float4 bb = *(const float4*)&bias[c];
        float4 gg = *(const float4*)&gamma[c];
        float4 be = *(const float4*)&beta[c];
        float4 mm = *(const float4*)&mean[c];
        float4 vv = *(const float4*)&var[c];
        float s0 = gg.x * rsqrtf(vv.x + 1e-5f);
        float s1 = gg.y * rsqrtf(vv.y + 1e-5f);
        float s2 = gg.z * rsqrtf(vv.z + 1e-5f);
        float s3 = gg.w * rsqrtf(vv.w + 1e-5f);
        float y0 = fmaxf((acc[4 * h + 0] + bb.x - mm.x) * s0 + be.x, 0.0f);
        float y1 = fmaxf((acc[4 * h + 1] + bb.y - mm.y) * s1 + be.y, 0.0f);
        float y2 = fmaxf((acc[4 * h + 2] + bb.z - mm.z) * s2 + be.z, 0.0f);
        float y3 = fmaxf((acc[4 * h + 3] + bb.w - mm.w) * s3 + be.w, 0.0f);
        pk.h2[2 * h]     = __floats2half2_rn(y0, y1);
        pk.h2[2 * h + 1] = __floats2half2_rn(y2, y3);
    }
    *(uint4*)&out[(size_t)node * 128 + c0] = pk.v;
}

// ---------------- fc via tensor cores: out[N,40] = [x0|x1|x2] @ fc_W + fc_b --------
__global__ __launch_bounds__(256) void fc_mma(const float* __restrict__ x0,
                                              const float* __restrict__ bias,
                                              float* __restrict__ out, int M) {
    extern __shared__ u32 sm[];
    u32* sAh = sm;
    u32* sAl = sm + 8192;

    int tid = threadIdx.x;
    int bm  = blockIdx.x * 128;
    int w = tid >> 5;
    int l = tid & 31;
    int g  = l >> 2;
    int b4 = l & 3;

    float c[5][4];
#pragma unroll
    for (int nt = 0; nt < 5; nt++) {
        float bv0 = bias[nt * 8 + b4 * 2];
        float bv1 = bias[nt * 8 + b4 * 2 + 1];
        c[nt][0] = bv0; c[nt][1] = bv1; c[nt][2] = bv0; c[nt][3] = bv1;
    }

    for (int s = 0; s < 3; s++) {
        if (s) __syncthreads();
        for (int i = tid; i < 8192; i += 256) {
            int row = i >> 6, kpair = i & 63;
            int gm = bm + row; if (gm >= M) gm = M - 1;
            float2 v;
            if (s == 0) {
                v = *(const float2*)&x0[(size_t)gm * 128 + 2 * kpair];
            } else {
                const __half* S = (s == 1) ? g_x1 : g_x2;
                __half2 hv = *(const __half2*)&S[(size_t)gm * 128 + 2 * kpair];
                v = __half22float2(hv);
            }
            __nv_bfloat16 hx = __float2bfloat16(v.x);
            __nv_bfloat16 hy = __float2bfloat16(v.y);
            __nv_bfloat16 lx = __float2bfloat16(v.x - __bfloat162float(hx));
            __nv_bfloat16 ly = __float2bfloat16(v.y - __bfloat162float(hy));
            int mt = row >> 4;
            int r  = row & 15;
            int gg = r & 7;
            int kt  = kpair >> 3;
            int kpj = kpair & 7;
            int bb  = kpj & 3;
            int reg = (r >> 3) | ((kpj >> 2) << 1);
            int lane = gg * 4 + bb;
            int idx = ((mt * 8 + kt) * 32 + lane) * 4 + reg;
            __nv_bfloat162 ph = __halves2bfloat162(hx, hy);
            __nv_bfloat162 pl = __halves2bfloat162(lx, ly);
            sAh[idx] = *(u32*)&ph;
            sAl[idx] = *(u32*)&pl;
        }
        __syncthreads();

#pragma unroll
        for (int kt = 0; kt < 8; kt++) {
            int ktg = s * 8 + kt;
            int aidx = ((w * 8 + kt) * 32 + l) * 4;
            uint4 ahv = *(const uint4*)&sAh[aidx];
            uint4 alv = *(const uint4*)&sAl[aidx];
            u32 ah[4] = {ahv.x, ahv.y, ahv.z, ahv.w};
            u32 al[4] = {alv.x, alv.y, alv.z, alv.w};
#pragma unroll
            for (int nt = 0; nt < 5; nt++) {
                int bidx = ((ktg * 5 + nt) * 32 + l);
                uint2 bh = *(const uint2*)&g_BhF[bidx * 2];
                uint2 bl = *(const uint2*)&g_BlF[bidx * 2];
                u32 bhv[2] = {bh.x, bh.y};
                u32 blv[2] = {bl.x, bl.y};
                mma_bf16(c[nt], ah, bhv);
                mma_bf16(c[nt], al, bhv);
                mma_bf16(c[nt], ah, blv);
            }
        }
    }

    int gm0 = bm + w * 16 + g;
    int gm1 = gm0 + 8;
#pragma unroll
    for (int nt = 0; nt < 5; nt++) {
        int col = nt * 8 + b4 * 2;
        if (gm0 < M) *(float2*)&out[(size_t)gm0 * 40 + col] = make_float2(c[nt][0], c[nt][1]);
        if (gm1 < M) *(float2*)&out[(size_t)gm1 * 40 + col] = make_float2(c[nt][2], c[nt][3]);
    }
}

// ---------------- launch ----------------
extern "C" void kernel_launch(void* const* d_in, const int* in_sizes, int n_in,
                              void* d_out, int out_size) {
    const float* x   = (const float*)d_in[0];
    const int*   ei  = (const int*)  d_in[1];
    const float* W1  = (const float*)d_in[2];
    const float* b1  = (const float*)d_in[3];
    const float* W2  = (const float*)d_in[4];
    const float* b2  = (const float*)d_in[5];
    const float* g1  = (const float*)d_in[6];
    const float* be1 = (const float*)d_in[7];
    const float* m1  = (const float*)d_in[8];
    const float* v1  = (const float*)d_in[9];
    const float* g2  = (const float*)d_in[10];
    const float* be2 = (const float*)d_in[11];
    const float* m2  = (const float*)d_in[12];
    const float* v2  = (const float*)d_in[13];
    const float* fcW = (const float*)d_in[14];
    const float* fcb = (const float*)d_in[15];
    float* out = (float*)d_out;

    int N = in_sizes[0] / 128;
    int E = in_sizes[1] / 2;
    const int* rows = ei;
    const int* cols = ei + E;

    cudaFuncSetAttribute(gemm_mma, cudaFuncAttributeMaxDynamicSharedMemorySize, SM_GT);
    cudaFuncSetAttribute(fc_mma,   cudaFuncAttributeMaxDynamicSharedMemorySize, SM_GT);

    int gblocks = (N + 127) / 128;           // 782
    int hblocks = (E + 255) / 256;           // 6250
    int nb = (N + 1023) / 1024;              // 98

    prep<<<188 + hblocks, 256>>>(W1, W2, fcW, rows, E);                // 0
    gemm_mma<<<gblocks, 256, SM_GT>>>(0, x, 0, N);                     // 1
    csr_fused<<<nb, 1024>>>(rows, cols, N, E, nb);                     // 2
    aggregate<<<(N + 15) / 16, 256>>>(b1, g1, be1, m1, v1, 1, N);      // 3 <- profiled
    gemm_mma<<<gblocks, 256, SM_GT>>>(1, x, 1, N);                     // 4
    aggregate<<<(N + 15) / 16, 256>>>(b2, g2, be2, m2, v2, 2, N);      // 5
    fc_mma<<<gblocks, 256, SM_GT>>>(x, fcb, out, N);                   // 6
}